// round 11
// baseline (speedup 1.0000x reference)
#include <cuda_runtime.h>
#include <cstdint>
#include <math.h>
#include <limits.h>

#define NC   64
#define NS   16
#define SCALE_XYZ 8388608    // 512*512*32
#define SCALE_YZ  16384      // 512*32
#define SCALE_Z   32
#define TOTAL_CELLS 33554432 // 4 * SCALE_XYZ
#define NWORDS (TOTAL_CELLS / 32)   // 1,048,576 bitmap words
#define NVB 1024             // virtual scan blocks: NWORDS / (256 thr * 4 words)
#define NPTS 1000000
#define NCSB 1024            // >= ceil(NPTS/1024)

// ---------------- scratch (device globals; no allocation allowed) -------------
__device__ unsigned int g_bits[NWORDS];        // occupancy bitmap
__device__ int   g_wpfx[NWORDS];               // exclusive rank prefix per word
__device__ int   g_code[NPTS];
__device__ int   g_inv[NPTS];
__device__ int   g_unq[NPTS];
__device__ int   g_icnt[NPTS];
__device__ int   g_off[NPTS + 1];
__device__ int   g_cur[NPTS];
__device__ int   g_pts[NPTS];
__device__ int   g_mlist[NPTS / 2 + 1];        // rows with count >= 2
__device__ int   g_mcnt;                       // number of multi rows
__device__ int   g_bsum[NVB];
__device__ int   g_bsum2[NCSB];
__device__ unsigned int g_barc;                // barrier ticket counter (monotonic)

// ---------------- software grid barrier (generation from monotonic ticket) ----
__device__ __forceinline__ void gsync() {
    __syncthreads();
    if (threadIdx.x == 0) {
        __threadfence();
        unsigned int nb = gridDim.x;
        unsigned int ticket = atomicAdd(&g_barc, 1u);
        unsigned int target = (ticket / nb + 1u) * nb;
        while (*(volatile unsigned int*)&g_barc < target) __nanosleep(64);
        __threadfence();
    }
    __syncthreads();
}

// =============================================================================
__global__ void __launch_bounds__(256)
k_fused(const float* __restrict__ mu, const float* __restrict__ sc,
        const float* __restrict__ rot, const float* __restrict__ ft,
        const float* __restrict__ sm, const int* __restrict__ bidx,
        float* __restrict__ out, int n) {
    __shared__ int sh[256];
    const int t   = threadIdx.x;
    const int gid = blockIdx.x * blockDim.x + t;
    const int gsz = gridDim.x * blockDim.x;

    // ---- S0: zero bitmap + multi counter -----------------------------------
    for (int i = gid; i < NWORDS; i += gsz) g_bits[i] = 0u;
    if (gid == 0) g_mcnt = 0;
    gsync();

    // ---- S1: voxel code + occupancy bit ------------------------------------
    for (int i = gid; i < n; i += gsz) {
        float x = mu[i*3+0], y = mu[i*3+1], z = mu[i*3+2];
        // must match XLA exactly: IEEE div, floor, int32 cast
        int ix = (int)floorf(__fdiv_rn(x - (-51.2f), 0.2f));
        int iy = (int)floorf(__fdiv_rn(y - (-51.2f), 0.2f));
        int iz = (int)floorf(__fdiv_rn(z - (-3.2f),  0.2f));
        int code = bidx[i] * SCALE_XYZ + iz * SCALE_YZ + iy * SCALE_Z + ix;
        g_code[i] = code;
        atomicOr(&g_bits[code >> 5], 1u << (code & 31));
    }
    gsync();

    // ---- S2: popcount sums (+ zero icnt/unq) --------------------------------
    for (int i = gid; i < n; i += gsz) { g_icnt[i] = 0; g_unq[i] = -1; }
    for (int vb = blockIdx.x; vb < NVB; vb += gridDim.x) {
        uint4 v = ((const uint4*)g_bits)[vb * 256 + t];
        int s = __popc(v.x) + __popc(v.y) + __popc(v.z) + __popc(v.w);
        sh[t] = s; __syncthreads();
        for (int o = 128; o > 0; o >>= 1) {
            if (t < o) sh[t] += sh[t + o];
            __syncthreads();
        }
        if (t == 0) g_bsum[vb] = sh[0];
        __syncthreads();
    }
    gsync();

    // ---- S3: scan 1024 block sums (block 0 only) ---------------------------
    if (blockIdx.x == 0) {
        int v[4]; int s = 0;
        #pragma unroll
        for (int j = 0; j < 4; j++) { v[j] = g_bsum[t*4 + j]; s += v[j]; }
        sh[t] = s; __syncthreads();
        for (int o = 1; o < 256; o <<= 1) {
            int val = (t >= o) ? sh[t - o] : 0;
            __syncthreads();
            sh[t] += val;
            __syncthreads();
        }
        int run = sh[t] - s;                 // exclusive
        #pragma unroll
        for (int j = 0; j < 4; j++) { g_bsum[t*4 + j] = run; run += v[j]; }
    }
    gsync();

    // ---- S4: word prefixes + sorted unique codes ---------------------------
    for (int vb = blockIdx.x; vb < NVB; vb += gridDim.x) {
        uint4 v = ((const uint4*)g_bits)[vb * 256 + t];
        int c0 = __popc(v.x), c1 = __popc(v.y), c2 = __popc(v.z), c3 = __popc(v.w);
        int s = c0 + c1 + c2 + c3;
        sh[t] = s; __syncthreads();
        for (int o = 1; o < 256; o <<= 1) {
            int val = (t >= o) ? sh[t - o] : 0;
            __syncthreads();
            sh[t] += val;
            __syncthreads();
        }
        int run = g_bsum[vb] + ((t == 0) ? 0 : sh[t - 1]);
        int wbase = vb * 1024 + t * 4;
        unsigned int w[4] = { v.x, v.y, v.z, v.w };
        int cnt[4] = { c0, c1, c2, c3 };
        #pragma unroll
        for (int j = 0; j < 4; j++) {
            g_wpfx[wbase + j] = run;
            unsigned int m = w[j];
            int cellbase = (wbase + j) << 5;
            int rr = run;
            while (m) {                      // LSB->MSB = ascending cell = ascending rank
                int b = __ffs(m) - 1;
                m &= m - 1;
                g_unq[rr++] = cellbase + b;
            }
            run += cnt[j];
        }
        __syncthreads();
    }
    gsync();

    // ---- S5: rank via popc + counts + multi-row list -----------------------
    for (int i = gid; i < n; i += gsz) {
        int code = g_code[i];
        unsigned int w = g_bits[code >> 5];
        int s = g_wpfx[code >> 5] + __popc(w & ((1u << (code & 31)) - 1u));
        g_inv[i] = s;
        int old = atomicAdd(&g_icnt[s], 1);
        if (old == 1) {                      // exactly once per multi row
            int pos = atomicAdd(&g_mcnt, 1);
            g_mlist[pos] = s;
        }
    }
    gsync();

    // ---- S6: per-virtual-block count sums ----------------------------------
    const int cblk = (n + 1023) / 1024;
    for (int vb = blockIdx.x; vb < cblk; vb += gridDim.x) {
        int base = vb * 1024 + t * 4;
        int s = 0;
        if (base < n) {                      // n % 4 == 0
            int4 v = *(const int4*)&g_icnt[base];
            s = v.x + v.y + v.z + v.w;
        }
        sh[t] = s; __syncthreads();
        for (int o = 128; o > 0; o >>= 1) {
            if (t < o) sh[t] += sh[t + o];
            __syncthreads();
        }
        if (t == 0) g_bsum2[vb] = sh[0];
        __syncthreads();
    }
    gsync();

    // ---- S7: scan count block sums (block 0 only) --------------------------
    if (blockIdx.x == 0) {
        int v[4]; int s = 0;
        #pragma unroll
        for (int j = 0; j < 4; j++) {
            int idx = t*4 + j;
            v[j] = (idx < cblk) ? g_bsum2[idx] : 0;
            s += v[j];
        }
        sh[t] = s; __syncthreads();
        for (int o = 1; o < 256; o <<= 1) {
            int val = (t >= o) ? sh[t - o] : 0;
            __syncthreads();
            sh[t] += val;
            __syncthreads();
        }
        int run = sh[t] - s;                 // exclusive
        #pragma unroll
        for (int j = 0; j < 4; j++) {
            int idx = t*4 + j;
            if (idx < cblk) g_bsum2[idx] = run;
            run += v[j];
        }
    }
    gsync();

    // ---- S8: CSR offsets + cursors -----------------------------------------
    for (int vb = blockIdx.x; vb < cblk; vb += gridDim.x) {
        int base = vb * 1024 + t * 4;
        int4 v = make_int4(0, 0, 0, 0);
        if (base < n) v = *(const int4*)&g_icnt[base];
        int s = v.x + v.y + v.z + v.w;
        sh[t] = s; __syncthreads();
        for (int o = 1; o < 256; o <<= 1) {
            int val = (t >= o) ? sh[t - o] : 0;
            __syncthreads();
            sh[t] += val;
            __syncthreads();
        }
        int run = g_bsum2[vb] + ((t == 0) ? 0 : sh[t - 1]);
        if (base < n) {
            int e[4] = { v.x, v.y, v.z, v.w };
            #pragma unroll
            for (int j = 0; j < 4; j++) {
                g_off[base + j] = run;
                g_cur[base + j] = run;
                run += e[j];
                if (base + j == n - 1) g_off[n] = run;
            }
        }
        __syncthreads();
    }
    gsync();

    // ---- S9: scatter points into segment lists -----------------------------
    for (int i = gid; i < n; i += gsz) {
        int s = g_inv[i];
        int pos = atomicAdd(&g_cur[s], 1);
        g_pts[pos] = i;
    }
    gsync();

    // ======== S10: output (no barriers needed between sub-stages) ===========
    float*  out_mu  = out;
    float*  out_sc  = out + 3  * (size_t)n;
    float*  out_rot = out + 6  * (size_t)n;
    float2* out_ft2 = (float2*)(out + 10 * (size_t)n);
    float*  out_sm  = out + 74 * (size_t)n;
    float*  out_vx  = out + 90 * (size_t)n;
    const float2* ft2 = (const float2*)ft;

    // ---- S10-A: point-order singleton small fields (sequential reads) ------
    for (int p = gid; p < n; p += gsz) {
        int s = g_inv[p];
        if (g_icnt[s] == 1) {
            float m0 = __ldg(&mu[(size_t)p*3+0]);
            float m1 = __ldg(&mu[(size_t)p*3+1]);
            float m2 = __ldg(&mu[(size_t)p*3+2]);
            float4 q = __ldg((const float4*)&rot[(size_t)p*4]);
            float s0 = __ldg(&sc[(size_t)p*3+0]);
            float s1 = __ldg(&sc[(size_t)p*3+1]);
            float s2 = __ldg(&sc[(size_t)p*3+2]);
            out_mu[(size_t)s*3+0] = m0;
            out_mu[(size_t)s*3+1] = m1;
            out_mu[(size_t)s*3+2] = m2;
            float nrm = sqrtf(q.x*q.x + q.y*q.y + q.z*q.z + q.w*q.w);
            float dv = fmaxf(nrm, 1e-12f);
            *(float4*)&out_rot[(size_t)s*4] = make_float4(q.x/dv, q.y/dv, q.z/dv, q.w/dv);
            out_sc[(size_t)s*3+0] = s0;
            out_sc[(size_t)s*3+1] = s1;
            out_sc[(size_t)s*3+2] = s2;
        }
    }

    // ---- S10-B: point-order singleton ft + sem (sequential 256B reads) -----
    {
        const int lane = t & 31;
        const int w    = gid >> 5;
        const int W    = gsz >> 5;
        for (int p = w; p < n; p += W) {
            int s = g_inv[p];                 // broadcast
            if (g_icnt[s] == 1) {
                float2 f = __ldcs(&ft2[(size_t)p*32 + lane]);
                __stcs(&out_ft2[(size_t)s*32 + lane], f);
                if (lane < NS)
                    out_sm[(size_t)s*NS + lane] = __ldg(&sm[(size_t)p*NS + lane]);
            }
        }
    }

    // ---- S10-C: multi rows (count >= 2) via gather, warp-per-row -----------
    // lane map: 0-2 mu | 4-7 rot | 8-10 scale | 11-26 sem | all: ft float2
    {
        const int lane = t & 31;
        const int w    = gid >> 5;
        const int W    = gsz >> 5;
        const int mtot = g_mcnt;

        const float* gbase; int gstride, gsub;
        if (lane < 3)       { gbase = mu;  gstride = 3;  gsub = lane; }
        else if (lane < 8)  { gbase = rot; gstride = 4;  gsub = (lane - 4) & 3; }
        else if (lane < 11) { gbase = sc;  gstride = 3;  gsub = lane - 8; }
        else if (lane < 27) { gbase = sm;  gstride = 16; gsub = lane - 11; }
        else                { gbase = mu;  gstride = 0;  gsub = 0; }
        const bool isrot = (lane >= 4 && lane < 8);

        for (int mi = w; mi < mtot; mi += W) {
            int r = g_mlist[mi];
            int start = g_off[r];
            int end   = g_off[r + 1];
            int c     = end - start;

            int mn = INT_MAX;
            for (int j = start + lane; j < end; j += 32) mn = min(mn, g_pts[j]);
            mn = __reduce_min_sync(0xffffffffu, mn);
            float qc = 0.f;
            if (isrot) qc = __ldg(&rot[(size_t)mn*4 + (lane - 4)]);

            float a0 = 0.f, a1 = 0.f, am = 0.f;
            for (int j = start; j < end; j++) {
                int i = g_pts[j];
                float2 f = __ldcs(&ft2[(size_t)i*32 + lane]);
                a0 += f.x; a1 += f.y;
                float v = __ldg(&gbase[(size_t)i*gstride + gsub]);
                if (isrot) {
                    float p = v * qc;
                    p += __shfl_xor_sync(0x000000F0u, p, 1);
                    p += __shfl_xor_sync(0x000000F0u, p, 2);
                    float sg = (p + 1e-8f) >= 0.f ? 1.f : -1.f;
                    v *= sg;
                }
                am += v;
            }

            float inv_d = 1.0f / (float)c;
            __stcs(&out_ft2[(size_t)r*32 + lane], make_float2(a0*inv_d, a1*inv_d));
            if (lane < 3) {
                out_mu[(size_t)r*3 + lane] = am * inv_d;
            } else if (isrot) {
                float p = am * inv_d;
                float v = p * p;
                v += __shfl_xor_sync(0x000000F0u, v, 1);
                v += __shfl_xor_sync(0x000000F0u, v, 2);
                float nrm = sqrtf(v);
                out_rot[(size_t)r*4 + (lane - 4)] = p / fmaxf(nrm, 1e-12f);
            } else if (lane >= 8 && lane < 11) {
                out_sc[(size_t)r*3 + (lane - 8)] = am * inv_d;
            } else if (lane >= 11 && lane < 27) {
                out_sm[(size_t)r*NS + (lane - 11)] = am * inv_d;
            }
        }
    }

    // ---- S10-D: vox decode for all rows + zero-fill empty rows -------------
    for (int r = gid; r < n; r += gsz) {
        int u = g_unq[r];
        int vb, vz, vy, vx;
        if (u < 0) { vb = -1; vz = 511; vy = 511; vx = 31; }  // jnp semantics for -1
        else {
            vb = u / SCALE_XYZ; int rem = u % SCALE_XYZ;
            vz = rem / SCALE_YZ; rem %= SCALE_YZ;
            vy = rem / SCALE_Z;  vx = rem % SCALE_Z;
        }
        *(float4*)&out_vx[(size_t)r*4] =
            make_float4((float)vb, (float)vz, (float)vy, (float)vx);

        if (u < 0) {                         // empty padded row: zeros everywhere
            out_mu[(size_t)r*3+0] = 0.f; out_mu[(size_t)r*3+1] = 0.f; out_mu[(size_t)r*3+2] = 0.f;
            out_sc[(size_t)r*3+0] = 0.f; out_sc[(size_t)r*3+1] = 0.f; out_sc[(size_t)r*3+2] = 0.f;
            *(float4*)&out_rot[(size_t)r*4] = make_float4(0.f, 0.f, 0.f, 0.f);
            float4* smo = (float4*)&out_sm[(size_t)r*16];
            float4 z4 = make_float4(0.f, 0.f, 0.f, 0.f);
            smo[0] = z4; smo[1] = z4; smo[2] = z4; smo[3] = z4;
            float4* fo = (float4*)&out_ft2[(size_t)r*32];
            #pragma unroll
            for (int k = 0; k < 16; k++) fo[k] = z4;
        }
    }
}

// -----------------------------------------------------------------------------
extern "C" void kernel_launch(void* const* d_in, const int* in_sizes, int n_in,
                              void* d_out, int out_size) {
    const float* mu   = (const float*)d_in[0];
    const float* sc   = (const float*)d_in[1];
    const float* rot  = (const float*)d_in[2];
    const float* ft   = (const float*)d_in[3];
    const float* sm   = (const float*)d_in[4];
    const int*   bidx = (const int*)  d_in[5];
    float* out = (float*)d_out;
    int n = in_sizes[5];   // batch_idx element count == N

    int dev = 0;
    cudaGetDevice(&dev);
    int sms = 0;
    cudaDeviceGetAttribute(&sms, cudaDevAttrMultiProcessorCount, dev);
    int bpsm = 0;
    cudaOccupancyMaxActiveBlocksPerMultiprocessor(&bpsm, k_fused, 256, 0);
    if (bpsm < 1) bpsm = 1;
    if (sms < 1) sms = 1;
    int G = sms * bpsm;     // guaranteed co-resident -> software barrier is safe

    k_fused<<<G, 256>>>(mu, sc, rot, ft, sm, bidx, out, n);
}

// round 12
// speedup vs baseline: 1.2063x; 1.2063x over previous
#include <cuda_runtime.h>
#include <cstdint>
#include <math.h>
#include <limits.h>

#define NC   64
#define NS   16
#define SCALE_XYZ 8388608    // 512*512*32
#define SCALE_YZ  16384      // 512*32
#define SCALE_Z   32
#define TOTAL_CELLS 33554432 // 4 * SCALE_XYZ
#define NWORDS (TOTAL_CELLS / 32)   // 1,048,576 bitmap words
#define NVB 1024             // virtual scan blocks: NWORDS / (256 thr * 4 words)
#define NPTS 1000000
#define NCSB 1024            // >= ceil(NPTS/1024)

// ---------------- scratch (device globals; no allocation allowed) -------------
__device__ unsigned int g_bits[NWORDS];        // occupancy bitmap
__device__ int   g_wpfx[NWORDS];               // exclusive rank prefix per word
__device__ int   g_code[NPTS];
__device__ int   g_inv[NPTS];
__device__ int   g_unq[NPTS];
__device__ int   g_icnt[NPTS];
__device__ int   g_first[NPTS];                // min point index per row (atomicMin)
__device__ int   g_off[NPTS + 1];
__device__ int   g_cur[NPTS];
__device__ int   g_pts[NPTS];
__device__ int   g_bsum[NVB];
__device__ int   g_bsum2[NCSB];
__device__ unsigned int g_barc;                // barrier ticket counter (monotonic)

// ---------------- software grid barrier (generation from monotonic ticket) ----
__device__ __forceinline__ void gsync() {
    __syncthreads();
    if (threadIdx.x == 0) {
        __threadfence();
        unsigned int nb = gridDim.x;
        unsigned int ticket = atomicAdd(&g_barc, 1u);
        unsigned int target = (ticket / nb + 1u) * nb;
        while (*(volatile unsigned int*)&g_barc < target) __nanosleep(64);
        __threadfence();
    }
    __syncthreads();
}

// =============================================================================
__global__ void __launch_bounds__(256)
k_fused(const float* __restrict__ mu, const float* __restrict__ sc,
        const float* __restrict__ rot, const float* __restrict__ ft,
        const float* __restrict__ sm, const int* __restrict__ bidx,
        float* __restrict__ out, int n) {
    __shared__ int sh[256];
    const int t   = threadIdx.x;
    const int gid = blockIdx.x * blockDim.x + t;
    const int gsz = gridDim.x * blockDim.x;

    // ---- S0: zero bitmap ----------------------------------------------------
    for (int i = gid; i < NWORDS; i += gsz) g_bits[i] = 0u;
    gsync();

    // ---- S1: voxel code + occupancy bit ------------------------------------
    for (int i = gid; i < n; i += gsz) {
        float x = mu[i*3+0], y = mu[i*3+1], z = mu[i*3+2];
        // must match XLA exactly: IEEE div, floor, int32 cast
        int ix = (int)floorf(__fdiv_rn(x - (-51.2f), 0.2f));
        int iy = (int)floorf(__fdiv_rn(y - (-51.2f), 0.2f));
        int iz = (int)floorf(__fdiv_rn(z - (-3.2f),  0.2f));
        int code = bidx[i] * SCALE_XYZ + iz * SCALE_YZ + iy * SCALE_Z + ix;
        g_code[i] = code;
        atomicOr(&g_bits[code >> 5], 1u << (code & 31));
    }
    gsync();

    // ---- S2: popcount sums (+ init icnt/unq/first) --------------------------
    for (int i = gid; i < n; i += gsz) {
        g_icnt[i] = 0; g_unq[i] = -1; g_first[i] = INT_MAX;
    }
    for (int vb = blockIdx.x; vb < NVB; vb += gridDim.x) {
        uint4 v = ((const uint4*)g_bits)[vb * 256 + t];
        int s = __popc(v.x) + __popc(v.y) + __popc(v.z) + __popc(v.w);
        sh[t] = s; __syncthreads();
        for (int o = 128; o > 0; o >>= 1) {
            if (t < o) sh[t] += sh[t + o];
            __syncthreads();
        }
        if (t == 0) g_bsum[vb] = sh[0];
        __syncthreads();
    }
    gsync();

    // ---- S3: scan 1024 block sums (block 0 only) ---------------------------
    if (blockIdx.x == 0) {
        int v[4]; int s = 0;
        #pragma unroll
        for (int j = 0; j < 4; j++) { v[j] = g_bsum[t*4 + j]; s += v[j]; }
        sh[t] = s; __syncthreads();
        for (int o = 1; o < 256; o <<= 1) {
            int val = (t >= o) ? sh[t - o] : 0;
            __syncthreads();
            sh[t] += val;
            __syncthreads();
        }
        int run = sh[t] - s;                 // exclusive
        #pragma unroll
        for (int j = 0; j < 4; j++) { g_bsum[t*4 + j] = run; run += v[j]; }
    }
    gsync();

    // ---- S4: word prefixes + sorted unique codes ---------------------------
    for (int vb = blockIdx.x; vb < NVB; vb += gridDim.x) {
        uint4 v = ((const uint4*)g_bits)[vb * 256 + t];
        int c0 = __popc(v.x), c1 = __popc(v.y), c2 = __popc(v.z), c3 = __popc(v.w);
        int s = c0 + c1 + c2 + c3;
        sh[t] = s; __syncthreads();
        for (int o = 1; o < 256; o <<= 1) {
            int val = (t >= o) ? sh[t - o] : 0;
            __syncthreads();
            sh[t] += val;
            __syncthreads();
        }
        int run = g_bsum[vb] + ((t == 0) ? 0 : sh[t - 1]);
        int wbase = vb * 1024 + t * 4;
        unsigned int w[4] = { v.x, v.y, v.z, v.w };
        int cnt[4] = { c0, c1, c2, c3 };
        #pragma unroll
        for (int j = 0; j < 4; j++) {
            g_wpfx[wbase + j] = run;
            unsigned int m = w[j];
            int cellbase = (wbase + j) << 5;
            int rr = run;
            while (m) {                      // LSB->MSB = ascending cell = ascending rank
                int b = __ffs(m) - 1;
                m &= m - 1;
                g_unq[rr++] = cellbase + b;
            }
            run += cnt[j];
        }
        __syncthreads();
    }
    gsync();

    // ---- S5: rank via popc + counts + min point index -----------------------
    for (int i = gid; i < n; i += gsz) {
        int code = g_code[i];
        unsigned int w = g_bits[code >> 5];
        int s = g_wpfx[code >> 5] + __popc(w & ((1u << (code & 31)) - 1u));
        g_inv[i] = s;
        atomicAdd(&g_icnt[s], 1);
        atomicMin(&g_first[s], i);
    }
    gsync();

    // ---- S6: per-virtual-block count sums ----------------------------------
    const int cblk = (n + 1023) / 1024;
    for (int vb = blockIdx.x; vb < cblk; vb += gridDim.x) {
        int base = vb * 1024 + t * 4;
        int s = 0;
        if (base < n) {                      // n % 4 == 0
            int4 v = *(const int4*)&g_icnt[base];
            s = v.x + v.y + v.z + v.w;
        }
        sh[t] = s; __syncthreads();
        for (int o = 128; o > 0; o >>= 1) {
            if (t < o) sh[t] += sh[t + o];
            __syncthreads();
        }
        if (t == 0) g_bsum2[vb] = sh[0];
        __syncthreads();
    }
    gsync();

    // ---- S7: scan count block sums (block 0 only) --------------------------
    if (blockIdx.x == 0) {
        int v[4]; int s = 0;
        #pragma unroll
        for (int j = 0; j < 4; j++) {
            int idx = t*4 + j;
            v[j] = (idx < cblk) ? g_bsum2[idx] : 0;
            s += v[j];
        }
        sh[t] = s; __syncthreads();
        for (int o = 1; o < 256; o <<= 1) {
            int val = (t >= o) ? sh[t - o] : 0;
            __syncthreads();
            sh[t] += val;
            __syncthreads();
        }
        int run = sh[t] - s;                 // exclusive
        #pragma unroll
        for (int j = 0; j < 4; j++) {
            int idx = t*4 + j;
            if (idx < cblk) g_bsum2[idx] = run;
            run += v[j];
        }
    }
    gsync();

    // ---- S8: CSR offsets + cursors -----------------------------------------
    for (int vb = blockIdx.x; vb < cblk; vb += gridDim.x) {
        int base = vb * 1024 + t * 4;
        int4 v = make_int4(0, 0, 0, 0);
        if (base < n) v = *(const int4*)&g_icnt[base];
        int s = v.x + v.y + v.z + v.w;
        sh[t] = s; __syncthreads();
        for (int o = 1; o < 256; o <<= 1) {
            int val = (t >= o) ? sh[t - o] : 0;
            __syncthreads();
            sh[t] += val;
            __syncthreads();
        }
        int run = g_bsum2[vb] + ((t == 0) ? 0 : sh[t - 1]);
        if (base < n) {
            int e[4] = { v.x, v.y, v.z, v.w };
            #pragma unroll
            for (int j = 0; j < 4; j++) {
                g_off[base + j] = run;
                g_cur[base + j] = run;
                run += e[j];
                if (base + j == n - 1) g_off[n] = run;
            }
        }
        __syncthreads();
    }
    gsync();

    // ---- S9: scatter points into segment lists (multi rows need this) ------
    for (int i = gid; i < n; i += gsz) {
        int s = g_inv[i];
        int pos = atomicAdd(&g_cur[s], 1);
        g_pts[pos] = i;
    }
    gsync();

    // ======== S10: output (no barriers needed between sub-stages) ===========
    float*  out_mu  = out;
    float*  out_sc  = out + 3  * (size_t)n;
    float*  out_rot = out + 6  * (size_t)n;
    float2* out_ft2 = (float2*)(out + 10 * (size_t)n);
    float*  out_sm  = out + 74 * (size_t)n;
    float*  out_vx  = out + 90 * (size_t)n;
    const float2* ft2 = (const float2*)ft;

    // ---- S10a: THREAD-per-row small fields + vox ---------------------------
    // chain: coalesced icnt/first -> random gather -> coalesced store
    for (int r = gid; r < n; r += gsz) {
        int c = g_icnt[r];                    // coalesced
        int p = g_first[r];                   // coalesced, independent

        float m0=0.f,m1=0.f,m2=0.f, s0=0.f,s1=0.f,s2=0.f;
        float r0=0.f,r1=0.f,r2=0.f,r3=0.f;

        if (c == 1) {
            m0 = __ldg(&mu[(size_t)p*3+0]);
            m1 = __ldg(&mu[(size_t)p*3+1]);
            m2 = __ldg(&mu[(size_t)p*3+2]);
            float4 q = __ldg((const float4*)&rot[(size_t)p*4]);
            r0=q.x; r1=q.y; r2=q.z; r3=q.w;  // sign(+|q|^2)=+1
            s0 = __ldg(&sc[(size_t)p*3+0]);
            s1 = __ldg(&sc[(size_t)p*3+1]);
            s2 = __ldg(&sc[(size_t)p*3+2]);
        } else if (c > 1) {
            float4 qr = __ldg((const float4*)&rot[(size_t)p*4]);   // p = min index
            int start = g_off[r], end = g_off[r + 1];
            for (int j = start; j < end; j++) {
                int i = g_pts[j];
                m0 += __ldg(&mu[(size_t)i*3+0]);
                m1 += __ldg(&mu[(size_t)i*3+1]);
                m2 += __ldg(&mu[(size_t)i*3+2]);
                float4 q = __ldg((const float4*)&rot[(size_t)i*4]);
                float d = q.x*qr.x + q.y*qr.y + q.z*qr.z + q.w*qr.w;
                float sg = (d + 1e-8f) >= 0.f ? 1.f : -1.f;
                r0 += q.x*sg; r1 += q.y*sg; r2 += q.z*sg; r3 += q.w*sg;
                s0 += __ldg(&sc[(size_t)i*3+0]);
                s1 += __ldg(&sc[(size_t)i*3+1]);
                s2 += __ldg(&sc[(size_t)i*3+2]);
            }
        }

        float inv_d = 1.0f / fmaxf((float)c, 1.0f);

        out_mu[(size_t)r*3+0] = m0*inv_d;
        out_mu[(size_t)r*3+1] = m1*inv_d;
        out_mu[(size_t)r*3+2] = m2*inv_d;

        float p0=r0*inv_d, p1=r1*inv_d, p2=r2*inv_d, p3=r3*inv_d;
        float nrm = sqrtf(p0*p0 + p1*p1 + p2*p2 + p3*p3);
        float dv = fmaxf(nrm, 1e-12f);
        *(float4*)&out_rot[(size_t)r*4] = make_float4(p0/dv, p1/dv, p2/dv, p3/dv);

        out_sc[(size_t)r*3+0] = s0*inv_d;
        out_sc[(size_t)r*3+1] = s1*inv_d;
        out_sc[(size_t)r*3+2] = s2*inv_d;

        int u = g_unq[r];
        int vb, vz, vy, vx;
        if (u < 0) { vb = -1; vz = 511; vy = 511; vx = 31; }  // jnp semantics for -1
        else {
            vb = u / SCALE_XYZ; int rem = u % SCALE_XYZ;
            vz = rem / SCALE_YZ; rem %= SCALE_YZ;
            vy = rem / SCALE_Z;  vx = rem % SCALE_Z;
        }
        *(float4*)&out_vx[(size_t)r*4] =
            make_float4((float)vb, (float)vz, (float)vy, (float)vx);
    }

    // ---- S10b: WARP-per-row ft (float2/lane) + sem (lanes 0-15) ------------
    {
        const int lane = t & 31;
        const int w    = gid >> 5;
        const int W    = gsz >> 5;
        const bool issem = (lane < NS);

        for (int r = w; r < n; r += W) {
            int c = g_icnt[r];                // broadcast (same addr all lanes)
            int p = g_first[r];               // broadcast, independent
            float2 acc = make_float2(0.f, 0.f);
            float  asm_ = 0.f;
            if (c == 1) {
                acc = __ldcs(&ft2[(size_t)p*32 + lane]);   // exact copy
                if (issem) asm_ = __ldg(&sm[(size_t)p*NS + lane]);
            } else if (c > 1) {
                int start = g_off[r], end = g_off[r + 1];
                for (int j = start; j < end; j++) {
                    int i = g_pts[j];
                    float2 f = __ldcs(&ft2[(size_t)i*32 + lane]);
                    acc.x += f.x; acc.y += f.y;
                    if (issem) asm_ += __ldg(&sm[(size_t)i*NS + lane]);
                }
                float inv_d = 1.0f / (float)c;
                acc.x *= inv_d; acc.y *= inv_d;
                asm_ *= inv_d;
            }
            __stcs(&out_ft2[(size_t)r*32 + lane], acc);
            if (issem) out_sm[(size_t)r*NS + lane] = asm_;
        }
    }
}

// -----------------------------------------------------------------------------
extern "C" void kernel_launch(void* const* d_in, const int* in_sizes, int n_in,
                              void* d_out, int out_size) {
    const float* mu   = (const float*)d_in[0];
    const float* sc   = (const float*)d_in[1];
    const float* rot  = (const float*)d_in[2];
    const float* ft   = (const float*)d_in[3];
    const float* sm   = (const float*)d_in[4];
    const int*   bidx = (const int*)  d_in[5];
    float* out = (float*)d_out;
    int n = in_sizes[5];   // batch_idx element count == N

    int dev = 0;
    cudaGetDevice(&dev);
    int sms = 0;
    cudaDeviceGetAttribute(&sms, cudaDevAttrMultiProcessorCount, dev);
    int bpsm = 0;
    cudaOccupancyMaxActiveBlocksPerMultiprocessor(&bpsm, k_fused, 256, 0);
    if (bpsm < 1) bpsm = 1;
    if (sms < 1) sms = 1;
    int G = sms * bpsm;     // guaranteed co-resident -> software barrier is safe

    k_fused<<<G, 256>>>(mu, sc, rot, ft, sm, bidx, out, n);
}

// round 13
// speedup vs baseline: 1.3269x; 1.1000x over previous
#include <cuda_runtime.h>
#include <cstdint>
#include <math.h>
#include <limits.h>

#define NC   64
#define NS   16
#define SCALE_XYZ 8388608    // 512*512*32
#define SCALE_YZ  16384      // 512*32
#define SCALE_Z   32
#define TOTAL_CELLS 33554432 // 4 * SCALE_XYZ
#define NWORDS (TOTAL_CELLS / 32)   // 1,048,576 bitmap words
#define NVB 1024             // virtual scan blocks: NWORDS / (256 thr * 4 words)
#define NPTS 1000000
#define NCSB 1024            // >= ceil(NPTS/1024)

// ---------------- scratch (device globals; no allocation allowed) -------------
__device__ unsigned int g_bits[NWORDS];        // occupancy bitmap
__device__ int   g_wpfx[NWORDS];               // exclusive rank prefix per word
__device__ int   g_code[NPTS];
__device__ int   g_inv[NPTS];
__device__ int   g_unq[NPTS];
__device__ int   g_icnt[NPTS];
__device__ int   g_off[NPTS + 1];
__device__ int   g_cur[NPTS];
__device__ int   g_pts[NPTS];
__device__ int   g_bsum[NVB];
__device__ int   g_bsum2[NCSB];
__device__ unsigned int g_barc;                // barrier ticket counter (monotonic)

// ---------------- software grid barrier (generation from monotonic ticket) ----
__device__ __forceinline__ void gsync() {
    __syncthreads();
    if (threadIdx.x == 0) {
        __threadfence();
        unsigned int nb = gridDim.x;
        unsigned int ticket = atomicAdd(&g_barc, 1u);
        unsigned int target = (ticket / nb + 1u) * nb;
        while (*(volatile unsigned int*)&g_barc < target) __nanosleep(64);
        __threadfence();
    }
    __syncthreads();
}

// =============================================================================
__global__ void __launch_bounds__(256, 8)      // cap regs at 32 -> 2048 thr/SM
k_fused(const float* __restrict__ mu, const float* __restrict__ sc,
        const float* __restrict__ rot, const float* __restrict__ ft,
        const float* __restrict__ sm, const int* __restrict__ bidx,
        float* __restrict__ out, int n) {
    __shared__ int sh[256];
    const int t   = threadIdx.x;
    const int gid = blockIdx.x * blockDim.x + t;
    const int gsz = gridDim.x * blockDim.x;

    // ---- S0: zero bitmap ----------------------------------------------------
    for (int i = gid; i < NWORDS; i += gsz) g_bits[i] = 0u;
    gsync();

    // ---- S1: voxel code + occupancy bit ------------------------------------
    for (int i = gid; i < n; i += gsz) {
        float x = mu[i*3+0], y = mu[i*3+1], z = mu[i*3+2];
        // must match XLA exactly: IEEE div, floor, int32 cast
        int ix = (int)floorf(__fdiv_rn(x - (-51.2f), 0.2f));
        int iy = (int)floorf(__fdiv_rn(y - (-51.2f), 0.2f));
        int iz = (int)floorf(__fdiv_rn(z - (-3.2f),  0.2f));
        int code = bidx[i] * SCALE_XYZ + iz * SCALE_YZ + iy * SCALE_Z + ix;
        g_code[i] = code;
        atomicOr(&g_bits[code >> 5], 1u << (code & 31));
    }
    gsync();

    // ---- S2: popcount sums (+ zero icnt/unq) --------------------------------
    for (int i = gid; i < n; i += gsz) { g_icnt[i] = 0; g_unq[i] = -1; }
    for (int vb = blockIdx.x; vb < NVB; vb += gridDim.x) {
        uint4 v = ((const uint4*)g_bits)[vb * 256 + t];
        int s = __popc(v.x) + __popc(v.y) + __popc(v.z) + __popc(v.w);
        sh[t] = s; __syncthreads();
        for (int o = 128; o > 0; o >>= 1) {
            if (t < o) sh[t] += sh[t + o];
            __syncthreads();
        }
        if (t == 0) g_bsum[vb] = sh[0];
        __syncthreads();
    }
    gsync();

    // ---- S3: scan 1024 block sums (block 0 only) ---------------------------
    if (blockIdx.x == 0) {
        int v[4]; int s = 0;
        #pragma unroll
        for (int j = 0; j < 4; j++) { v[j] = g_bsum[t*4 + j]; s += v[j]; }
        sh[t] = s; __syncthreads();
        for (int o = 1; o < 256; o <<= 1) {
            int val = (t >= o) ? sh[t - o] : 0;
            __syncthreads();
            sh[t] += val;
            __syncthreads();
        }
        int run = sh[t] - s;                 // exclusive
        #pragma unroll
        for (int j = 0; j < 4; j++) { g_bsum[t*4 + j] = run; run += v[j]; }
    }
    gsync();

    // ---- S4: word prefixes + sorted unique codes ---------------------------
    for (int vb = blockIdx.x; vb < NVB; vb += gridDim.x) {
        uint4 v = ((const uint4*)g_bits)[vb * 256 + t];
        int c0 = __popc(v.x), c1 = __popc(v.y), c2 = __popc(v.z), c3 = __popc(v.w);
        int s = c0 + c1 + c2 + c3;
        sh[t] = s; __syncthreads();
        for (int o = 1; o < 256; o <<= 1) {
            int val = (t >= o) ? sh[t - o] : 0;
            __syncthreads();
            sh[t] += val;
            __syncthreads();
        }
        int run = g_bsum[vb] + ((t == 0) ? 0 : sh[t - 1]);
        int wbase = vb * 1024 + t * 4;
        unsigned int w[4] = { v.x, v.y, v.z, v.w };
        int cnt[4] = { c0, c1, c2, c3 };
        #pragma unroll
        for (int j = 0; j < 4; j++) {
            g_wpfx[wbase + j] = run;
            unsigned int m = w[j];
            int cellbase = (wbase + j) << 5;
            int rr = run;
            while (m) {                      // LSB->MSB = ascending cell = ascending rank
                int b = __ffs(m) - 1;
                m &= m - 1;
                g_unq[rr++] = cellbase + b;
            }
            run += cnt[j];
        }
        __syncthreads();
    }
    gsync();

    // ---- S5: rank via popc + segment counts --------------------------------
    for (int i = gid; i < n; i += gsz) {
        int code = g_code[i];
        unsigned int w = g_bits[code >> 5];
        int s = g_wpfx[code >> 5] + __popc(w & ((1u << (code & 31)) - 1u));
        g_inv[i] = s;
        atomicAdd(&g_icnt[s], 1);
    }
    gsync();

    // ---- S6: per-virtual-block count sums ----------------------------------
    const int cblk = (n + 1023) / 1024;
    for (int vb = blockIdx.x; vb < cblk; vb += gridDim.x) {
        int base = vb * 1024 + t * 4;
        int s = 0;
        if (base < n) {                      // n % 4 == 0
            int4 v = *(const int4*)&g_icnt[base];
            s = v.x + v.y + v.z + v.w;
        }
        sh[t] = s; __syncthreads();
        for (int o = 128; o > 0; o >>= 1) {
            if (t < o) sh[t] += sh[t + o];
            __syncthreads();
        }
        if (t == 0) g_bsum2[vb] = sh[0];
        __syncthreads();
    }
    gsync();

    // ---- S7: scan count block sums (block 0 only) --------------------------
    if (blockIdx.x == 0) {
        int v[4]; int s = 0;
        #pragma unroll
        for (int j = 0; j < 4; j++) {
            int idx = t*4 + j;
            v[j] = (idx < cblk) ? g_bsum2[idx] : 0;
            s += v[j];
        }
        sh[t] = s; __syncthreads();
        for (int o = 1; o < 256; o <<= 1) {
            int val = (t >= o) ? sh[t - o] : 0;
            __syncthreads();
            sh[t] += val;
            __syncthreads();
        }
        int run = sh[t] - s;                 // exclusive
        #pragma unroll
        for (int j = 0; j < 4; j++) {
            int idx = t*4 + j;
            if (idx < cblk) g_bsum2[idx] = run;
            run += v[j];
        }
    }
    gsync();

    // ---- S8: CSR offsets + cursors -----------------------------------------
    for (int vb = blockIdx.x; vb < cblk; vb += gridDim.x) {
        int base = vb * 1024 + t * 4;
        int4 v = make_int4(0, 0, 0, 0);
        if (base < n) v = *(const int4*)&g_icnt[base];
        int s = v.x + v.y + v.z + v.w;
        sh[t] = s; __syncthreads();
        for (int o = 1; o < 256; o <<= 1) {
            int val = (t >= o) ? sh[t - o] : 0;
            __syncthreads();
            sh[t] += val;
            __syncthreads();
        }
        int run = g_bsum2[vb] + ((t == 0) ? 0 : sh[t - 1]);
        if (base < n) {
            int e[4] = { v.x, v.y, v.z, v.w };
            #pragma unroll
            for (int j = 0; j < 4; j++) {
                g_off[base + j] = run;
                g_cur[base + j] = run;
                run += e[j];
                if (base + j == n - 1) g_off[n] = run;
            }
        }
        __syncthreads();
    }
    gsync();

    // ---- S9: scatter points into segment lists -----------------------------
    for (int i = gid; i < n; i += gsz) {
        int s = g_inv[i];
        int pos = atomicAdd(&g_cur[s], 1);
        g_pts[pos] = i;
    }
    gsync();

    // ---- S10a: THREAD-per-row small fields (mu, sc, rot, vox) --------------
    {
        float*  out_mu  = out;
        float*  out_sc  = out + 3  * (size_t)n;
        float*  out_rot = out + 6  * (size_t)n;
        float*  out_vx  = out + 90 * (size_t)n;

        for (int r = gid; r < n; r += gsz) {
            int start = g_off[r];
            int end   = g_off[r + 1];
            int c     = end - start;

            float m0=0.f,m1=0.f,m2=0.f, s0=0.f,s1=0.f,s2=0.f;
            float r0=0.f,r1=0.f,r2=0.f,r3=0.f;

            if (c == 1) {
                int i = g_pts[start];
                m0 = __ldg(&mu[(size_t)i*3+0]);
                m1 = __ldg(&mu[(size_t)i*3+1]);
                m2 = __ldg(&mu[(size_t)i*3+2]);
                float4 q = __ldg((const float4*)&rot[(size_t)i*4]);
                r0=q.x; r1=q.y; r2=q.z; r3=q.w;  // sign(+|q|^2)=+1
                s0 = __ldg(&sc[(size_t)i*3+0]);
                s1 = __ldg(&sc[(size_t)i*3+1]);
                s2 = __ldg(&sc[(size_t)i*3+2]);
            } else if (c > 1) {
                int mn = INT_MAX;
                for (int j = start; j < end; j++) mn = min(mn, g_pts[j]);
                float4 qr = __ldg((const float4*)&rot[(size_t)mn*4]);
                for (int j = start; j < end; j++) {
                    int i = g_pts[j];
                    m0 += __ldg(&mu[(size_t)i*3+0]);
                    m1 += __ldg(&mu[(size_t)i*3+1]);
                    m2 += __ldg(&mu[(size_t)i*3+2]);
                    float4 q = __ldg((const float4*)&rot[(size_t)i*4]);
                    float d = q.x*qr.x + q.y*qr.y + q.z*qr.z + q.w*qr.w;
                    float sg = (d + 1e-8f) >= 0.f ? 1.f : -1.f;
                    r0 += q.x*sg; r1 += q.y*sg; r2 += q.z*sg; r3 += q.w*sg;
                    s0 += __ldg(&sc[(size_t)i*3+0]);
                    s1 += __ldg(&sc[(size_t)i*3+1]);
                    s2 += __ldg(&sc[(size_t)i*3+2]);
                }
            }

            float inv_d = 1.0f / fmaxf((float)c, 1.0f);

            out_mu[(size_t)r*3+0] = m0*inv_d;
            out_mu[(size_t)r*3+1] = m1*inv_d;
            out_mu[(size_t)r*3+2] = m2*inv_d;

            float p0=r0*inv_d, p1=r1*inv_d, p2=r2*inv_d, p3=r3*inv_d;
            float nrm = sqrtf(p0*p0 + p1*p1 + p2*p2 + p3*p3);
            float dv = fmaxf(nrm, 1e-12f);
            *(float4*)&out_rot[(size_t)r*4] = make_float4(p0/dv, p1/dv, p2/dv, p3/dv);

            out_sc[(size_t)r*3+0] = s0*inv_d;
            out_sc[(size_t)r*3+1] = s1*inv_d;
            out_sc[(size_t)r*3+2] = s2*inv_d;

            int u = g_unq[r];
            int vb, vz, vy, vx;
            if (u < 0) { vb = -1; vz = 511; vy = 511; vx = 31; }  // jnp semantics for -1
            else {
                vb = u / SCALE_XYZ; int rem = u % SCALE_XYZ;
                vz = rem / SCALE_YZ; rem %= SCALE_YZ;
                vy = rem / SCALE_Z;  vx = rem % SCALE_Z;
            }
            *(float4*)&out_vx[(size_t)r*4] =
                make_float4((float)vb, (float)vz, (float)vy, (float)vx);
        }
    }

    // ---- S10b: WARP-per-row ft (float2/lane) + sem (lanes 0-15) ------------
    {
        const int lane = t & 31;
        const int w    = gid >> 5;
        const int W    = gsz >> 5;
        const float2* ft2     = (const float2*)ft;
        float2*       out_ft2 = (float2*)(out + 10 * (size_t)n);
        float*        out_sm  = out + 74 * (size_t)n;
        const bool issem = (lane < NS);

        for (int r = w; r < n; r += W) {
            int start = g_off[r];      // L2-hot after S10a
            int end   = g_off[r + 1];
            int c     = end - start;
            float2 acc = make_float2(0.f, 0.f);
            float  asm_ = 0.f;
            if (c == 1) {
                int i = g_pts[start];
                acc = __ldcs(&ft2[(size_t)i*32 + lane]);   // exact copy
                if (issem) asm_ = __ldg(&sm[(size_t)i*NS + lane]);
            } else if (c > 1) {
                for (int j = start; j < end; j++) {
                    int i = g_pts[j];
                    float2 f = __ldcs(&ft2[(size_t)i*32 + lane]);
                    acc.x += f.x; acc.y += f.y;
                    if (issem) asm_ += __ldg(&sm[(size_t)i*NS + lane]);
                }
                float inv_d = 1.0f / (float)c;
                acc.x *= inv_d; acc.y *= inv_d;
                asm_ *= inv_d;
            }
            __stcs(&out_ft2[(size_t)r*32 + lane], acc);
            if (issem) out_sm[(size_t)r*NS + lane] = asm_;
        }
    }
}

// -----------------------------------------------------------------------------
extern "C" void kernel_launch(void* const* d_in, const int* in_sizes, int n_in,
                              void* d_out, int out_size) {
    const float* mu   = (const float*)d_in[0];
    const float* sc   = (const float*)d_in[1];
    const float* rot  = (const float*)d_in[2];
    const float* ft   = (const float*)d_in[3];
    const float* sm   = (const float*)d_in[4];
    const int*   bidx = (const int*)  d_in[5];
    float* out = (float*)d_out;
    int n = in_sizes[5];   // batch_idx element count == N

    int dev = 0;
    cudaGetDevice(&dev);
    int sms = 0;
    cudaDeviceGetAttribute(&sms, cudaDevAttrMultiProcessorCount, dev);
    int bpsm = 0;
    cudaOccupancyMaxActiveBlocksPerMultiprocessor(&bpsm, k_fused, 256, 0);
    if (bpsm < 1) bpsm = 1;
    if (sms < 1) sms = 1;
    int G = sms * bpsm;     // guaranteed co-resident -> software barrier is safe

    k_fused<<<G, 256>>>(mu, sc, rot, ft, sm, bidx, out, n);
}

// round 14
// speedup vs baseline: 1.3306x; 1.0028x over previous
#include <cuda_runtime.h>
#include <cstdint>
#include <math.h>
#include <limits.h>

#define NC   64
#define NS   16
#define SCALE_XYZ 8388608    // 512*512*32
#define SCALE_YZ  16384      // 512*32
#define SCALE_Z   32
#define TOTAL_CELLS 33554432 // 4 * SCALE_XYZ
#define NWORDS (TOTAL_CELLS / 32)   // 1,048,576 bitmap words
#define NVB 1024             // virtual scan blocks: NWORDS / (256 thr * 4 words)
#define NPTS 1000000
#define NCSB 1024            // >= ceil(NPTS/1024)

// ---------------- scratch (device globals; no allocation allowed) -------------
__device__ unsigned int g_bits[NWORDS];        // occupancy bitmap
__device__ int   g_wpfx[NWORDS];               // exclusive rank prefix per word
__device__ int   g_code[NPTS];
__device__ int   g_inv[NPTS];
__device__ int   g_unq[NPTS];
__device__ int   g_icnt[NPTS];
__device__ int   g_off[NPTS + 1];
__device__ int   g_cur[NPTS];
__device__ int   g_pts[NPTS];
__device__ int   g_bsum[NVB];
__device__ int   g_bsum2[NCSB];
__device__ unsigned int g_barc;                // barrier ticket counter (monotonic)

// ---------------- software grid barrier (generation from monotonic ticket) ----
__device__ __forceinline__ void gsync() {
    __syncthreads();
    if (threadIdx.x == 0) {
        __threadfence();
        unsigned int nb = gridDim.x;
        unsigned int ticket = atomicAdd(&g_barc, 1u);
        unsigned int target = (ticket / nb + 1u) * nb;
        while (*(volatile unsigned int*)&g_barc < target) __nanosleep(64);
        __threadfence();
    }
    __syncthreads();
}

// =============================================================================
__global__ void __launch_bounds__(256, 8)      // cap regs at 32 -> 2048 thr/SM
k_fused(const float* __restrict__ mu, const float* __restrict__ sc,
        const float* __restrict__ rot, const float* __restrict__ ft,
        const float* __restrict__ sm, const int* __restrict__ bidx,
        float* __restrict__ out, int n) {
    __shared__ int sh[256];
    const int t   = threadIdx.x;
    const int gid = blockIdx.x * blockDim.x + t;
    const int gsz = gridDim.x * blockDim.x;

    // ---- S0: zero bitmap ----------------------------------------------------
    for (int i = gid; i < NWORDS; i += gsz) g_bits[i] = 0u;
    gsync();

    // ---- S1: voxel code + occupancy bit ------------------------------------
    for (int i = gid; i < n; i += gsz) {
        float x = mu[i*3+0], y = mu[i*3+1], z = mu[i*3+2];
        // must match XLA exactly: IEEE div, floor, int32 cast
        int ix = (int)floorf(__fdiv_rn(x - (-51.2f), 0.2f));
        int iy = (int)floorf(__fdiv_rn(y - (-51.2f), 0.2f));
        int iz = (int)floorf(__fdiv_rn(z - (-3.2f),  0.2f));
        int code = bidx[i] * SCALE_XYZ + iz * SCALE_YZ + iy * SCALE_Z + ix;
        g_code[i] = code;
        atomicOr(&g_bits[code >> 5], 1u << (code & 31));
    }
    gsync();

    // ---- S2: popcount sums (+ zero icnt/unq) --------------------------------
    for (int i = gid; i < n; i += gsz) { g_icnt[i] = 0; g_unq[i] = -1; }
    for (int vb = blockIdx.x; vb < NVB; vb += gridDim.x) {
        uint4 v = ((const uint4*)g_bits)[vb * 256 + t];
        int s = __popc(v.x) + __popc(v.y) + __popc(v.z) + __popc(v.w);
        sh[t] = s; __syncthreads();
        for (int o = 128; o > 0; o >>= 1) {
            if (t < o) sh[t] += sh[t + o];
            __syncthreads();
        }
        if (t == 0) g_bsum[vb] = sh[0];
        __syncthreads();
    }
    gsync();

    // ---- S3: scan 1024 block sums (block 0 only) ---------------------------
    if (blockIdx.x == 0) {
        int v[4]; int s = 0;
        #pragma unroll
        for (int j = 0; j < 4; j++) { v[j] = g_bsum[t*4 + j]; s += v[j]; }
        sh[t] = s; __syncthreads();
        for (int o = 1; o < 256; o <<= 1) {
            int val = (t >= o) ? sh[t - o] : 0;
            __syncthreads();
            sh[t] += val;
            __syncthreads();
        }
        int run = sh[t] - s;                 // exclusive
        #pragma unroll
        for (int j = 0; j < 4; j++) { g_bsum[t*4 + j] = run; run += v[j]; }
    }
    gsync();

    // ---- S4: word prefixes + sorted unique codes ---------------------------
    for (int vb = blockIdx.x; vb < NVB; vb += gridDim.x) {
        uint4 v = ((const uint4*)g_bits)[vb * 256 + t];
        int c0 = __popc(v.x), c1 = __popc(v.y), c2 = __popc(v.z), c3 = __popc(v.w);
        int s = c0 + c1 + c2 + c3;
        sh[t] = s; __syncthreads();
        for (int o = 1; o < 256; o <<= 1) {
            int val = (t >= o) ? sh[t - o] : 0;
            __syncthreads();
            sh[t] += val;
            __syncthreads();
        }
        int run = g_bsum[vb] + ((t == 0) ? 0 : sh[t - 1]);
        int wbase = vb * 1024 + t * 4;
        unsigned int w[4] = { v.x, v.y, v.z, v.w };
        int cnt[4] = { c0, c1, c2, c3 };
        #pragma unroll
        for (int j = 0; j < 4; j++) {
            g_wpfx[wbase + j] = run;
            unsigned int m = w[j];
            int cellbase = (wbase + j) << 5;
            int rr = run;
            while (m) {                      // LSB->MSB = ascending cell = ascending rank
                int b = __ffs(m) - 1;
                m &= m - 1;
                g_unq[rr++] = cellbase + b;
            }
            run += cnt[j];
        }
        __syncthreads();
    }
    gsync();

    // ---- S5: rank via popc + segment counts --------------------------------
    for (int i = gid; i < n; i += gsz) {
        int code = g_code[i];
        unsigned int w = g_bits[code >> 5];
        int s = g_wpfx[code >> 5] + __popc(w & ((1u << (code & 31)) - 1u));
        g_inv[i] = s;
        atomicAdd(&g_icnt[s], 1);
    }
    gsync();

    // ---- S6: per-virtual-block count sums ----------------------------------
    const int cblk = (n + 1023) / 1024;
    for (int vb = blockIdx.x; vb < cblk; vb += gridDim.x) {
        int base = vb * 1024 + t * 4;
        int s = 0;
        if (base < n) {                      // n % 4 == 0
            int4 v = *(const int4*)&g_icnt[base];
            s = v.x + v.y + v.z + v.w;
        }
        sh[t] = s; __syncthreads();
        for (int o = 128; o > 0; o >>= 1) {
            if (t < o) sh[t] += sh[t + o];
            __syncthreads();
        }
        if (t == 0) g_bsum2[vb] = sh[0];
        __syncthreads();
    }
    gsync();

    // ---- S7: scan count block sums (block 0 only) --------------------------
    if (blockIdx.x == 0) {
        int v[4]; int s = 0;
        #pragma unroll
        for (int j = 0; j < 4; j++) {
            int idx = t*4 + j;
            v[j] = (idx < cblk) ? g_bsum2[idx] : 0;
            s += v[j];
        }
        sh[t] = s; __syncthreads();
        for (int o = 1; o < 256; o <<= 1) {
            int val = (t >= o) ? sh[t - o] : 0;
            __syncthreads();
            sh[t] += val;
            __syncthreads();
        }
        int run = sh[t] - s;                 // exclusive
        #pragma unroll
        for (int j = 0; j < 4; j++) {
            int idx = t*4 + j;
            if (idx < cblk) g_bsum2[idx] = run;
            run += v[j];
        }
    }
    gsync();

    // ---- S8: CSR offsets + cursors -----------------------------------------
    for (int vb = blockIdx.x; vb < cblk; vb += gridDim.x) {
        int base = vb * 1024 + t * 4;
        int4 v = make_int4(0, 0, 0, 0);
        if (base < n) v = *(const int4*)&g_icnt[base];
        int s = v.x + v.y + v.z + v.w;
        sh[t] = s; __syncthreads();
        for (int o = 1; o < 256; o <<= 1) {
            int val = (t >= o) ? sh[t - o] : 0;
            __syncthreads();
            sh[t] += val;
            __syncthreads();
        }
        int run = g_bsum2[vb] + ((t == 0) ? 0 : sh[t - 1]);
        if (base < n) {
            int e[4] = { v.x, v.y, v.z, v.w };
            #pragma unroll
            for (int j = 0; j < 4; j++) {
                g_off[base + j] = run;
                g_cur[base + j] = run;
                run += e[j];
                if (base + j == n - 1) g_off[n] = run;
            }
        }
        __syncthreads();
    }
    gsync();

    // ---- S9: scatter points into segment lists -----------------------------
    for (int i = gid; i < n; i += gsz) {
        int s = g_inv[i];
        int pos = atomicAdd(&g_cur[s], 1);
        g_pts[pos] = i;
    }
    gsync();

    // ---- S10a: THREAD-per-row small fields (mu, sc, rot, vox) --------------
    {
        float*  out_mu  = out;
        float*  out_sc  = out + 3  * (size_t)n;
        float*  out_rot = out + 6  * (size_t)n;
        float*  out_vx  = out + 90 * (size_t)n;

        for (int r = gid; r < n; r += gsz) {
            int start = g_off[r];
            int end   = g_off[r + 1];
            int c     = end - start;

            float m0=0.f,m1=0.f,m2=0.f, s0=0.f,s1=0.f,s2=0.f;
            float r0=0.f,r1=0.f,r2=0.f,r3=0.f;

            if (c == 1) {
                int i = g_pts[start];
                m0 = __ldg(&mu[(size_t)i*3+0]);
                m1 = __ldg(&mu[(size_t)i*3+1]);
                m2 = __ldg(&mu[(size_t)i*3+2]);
                float4 q = __ldg((const float4*)&rot[(size_t)i*4]);
                r0=q.x; r1=q.y; r2=q.z; r3=q.w;  // sign(+|q|^2)=+1
                s0 = __ldg(&sc[(size_t)i*3+0]);
                s1 = __ldg(&sc[(size_t)i*3+1]);
                s2 = __ldg(&sc[(size_t)i*3+2]);
            } else if (c > 1) {
                int mn = INT_MAX;
                for (int j = start; j < end; j++) mn = min(mn, g_pts[j]);
                float4 qr = __ldg((const float4*)&rot[(size_t)mn*4]);
                for (int j = start; j < end; j++) {
                    int i = g_pts[j];
                    m0 += __ldg(&mu[(size_t)i*3+0]);
                    m1 += __ldg(&mu[(size_t)i*3+1]);
                    m2 += __ldg(&mu[(size_t)i*3+2]);
                    float4 q = __ldg((const float4*)&rot[(size_t)i*4]);
                    float d = q.x*qr.x + q.y*qr.y + q.z*qr.z + q.w*qr.w;
                    float sg = (d + 1e-8f) >= 0.f ? 1.f : -1.f;
                    r0 += q.x*sg; r1 += q.y*sg; r2 += q.z*sg; r3 += q.w*sg;
                    s0 += __ldg(&sc[(size_t)i*3+0]);
                    s1 += __ldg(&sc[(size_t)i*3+1]);
                    s2 += __ldg(&sc[(size_t)i*3+2]);
                }
            }

            float inv_d = 1.0f / fmaxf((float)c, 1.0f);

            out_mu[(size_t)r*3+0] = m0*inv_d;
            out_mu[(size_t)r*3+1] = m1*inv_d;
            out_mu[(size_t)r*3+2] = m2*inv_d;

            float p0=r0*inv_d, p1=r1*inv_d, p2=r2*inv_d, p3=r3*inv_d;
            float nrm = sqrtf(p0*p0 + p1*p1 + p2*p2 + p3*p3);
            float dv = fmaxf(nrm, 1e-12f);
            *(float4*)&out_rot[(size_t)r*4] = make_float4(p0/dv, p1/dv, p2/dv, p3/dv);

            out_sc[(size_t)r*3+0] = s0*inv_d;
            out_sc[(size_t)r*3+1] = s1*inv_d;
            out_sc[(size_t)r*3+2] = s2*inv_d;

            int u = g_unq[r];
            int vb, vz, vy, vx;
            if (u < 0) { vb = -1; vz = 511; vy = 511; vx = 31; }  // jnp semantics for -1
            else {
                vb = u / SCALE_XYZ; int rem = u % SCALE_XYZ;
                vz = rem / SCALE_YZ; rem %= SCALE_YZ;
                vy = rem / SCALE_Z;  vx = rem % SCALE_Z;
            }
            *(float4*)&out_vx[(size_t)r*4] =
                make_float4((float)vb, (float)vz, (float)vy, (float)vx);
        }
    }

    // ---- S10b: WARP-per-row ft (float2/lane) + sem (lanes 0-15) ------------
    {
        const int lane = t & 31;
        const int w    = gid >> 5;
        const int W    = gsz >> 5;
        const float2* ft2     = (const float2*)ft;
        float2*       out_ft2 = (float2*)(out + 10 * (size_t)n);
        float*        out_sm  = out + 74 * (size_t)n;
        const bool issem = (lane < NS);

        for (int r = w; r < n; r += W) {
            int start = g_off[r];      // L2-hot after S10a
            int end   = g_off[r + 1];
            int c     = end - start;
            float2 acc = make_float2(0.f, 0.f);
            float  asm_ = 0.f;
            if (c == 1) {
                int i = g_pts[start];
                acc = __ldcs(&ft2[(size_t)i*32 + lane]);   // exact copy
                if (issem) asm_ = __ldg(&sm[(size_t)i*NS + lane]);
            } else if (c > 1) {
                for (int j = start; j < end; j++) {
                    int i = g_pts[j];
                    float2 f = __ldcs(&ft2[(size_t)i*32 + lane]);
                    acc.x += f.x; acc.y += f.y;
                    if (issem) asm_ += __ldg(&sm[(size_t)i*NS + lane]);
                }
                float inv_d = 1.0f / (float)c;
                acc.x *= inv_d; acc.y *= inv_d;
                asm_ *= inv_d;
            }
            __stcs(&out_ft2[(size_t)r*32 + lane], acc);
            if (issem) out_sm[(size_t)r*NS + lane] = asm_;
        }
    }
}

// -----------------------------------------------------------------------------
extern "C" void kernel_launch(void* const* d_in, const int* in_sizes, int n_in,
                              void* d_out, int out_size) {
    const float* mu   = (const float*)d_in[0];
    const float* sc   = (const float*)d_in[1];
    const float* rot  = (const float*)d_in[2];
    const float* ft   = (const float*)d_in[3];
    const float* sm   = (const float*)d_in[4];
    const int*   bidx = (const int*)  d_in[5];
    float* out = (float*)d_out;
    int n = in_sizes[5];   // batch_idx element count == N

    int dev = 0;
    cudaGetDevice(&dev);
    int sms = 0;
    cudaDeviceGetAttribute(&sms, cudaDevAttrMultiProcessorCount, dev);
    int bpsm = 0;
    cudaOccupancyMaxActiveBlocksPerMultiprocessor(&bpsm, k_fused, 256, 0);
    if (bpsm < 1) bpsm = 1;
    if (sms < 1) sms = 1;
    int G = sms * bpsm;     // guaranteed co-resident -> software barrier is safe

    k_fused<<<G, 256>>>(mu, sc, rot, ft, sm, bidx, out, n);
}